// round 5
// baseline (speedup 1.0000x reference)
#include <cuda_runtime.h>
#include <math.h>
#include <stdint.h>

// Problem constants
#define Bb   16
#define Tt   512
#define Dd   2048
#define Hh   4
#define HDd  512
#define BT   8192          // B*T rows
#define NQKV 6144          // 3*D
#define DFF  8192          // 4*D
#define LNEPS 1e-5f

// ---------------------------------------------------------------------------
// Scratch (static __device__ arrays; no allocation allowed)
// ---------------------------------------------------------------------------
__device__ __align__(128) float g_Wqkv[(size_t)Dd * NQKV];
__device__ __align__(128) float g_ln[(size_t)BT * Dd];
__device__ __align__(128) float g_qkv[(size_t)BT * NQKV];
__device__ __align__(128) float g_scores[(size_t)Bb * Hh * Tt * Tt];
__device__ __align__(128) float g_ctx[(size_t)BT * Dd];
__device__ __align__(128) float g_ffn[(size_t)BT * DFF];
__device__ __align__(128) float g_Wot[(size_t)Dd * Dd];
__device__ __align__(128) float g_W1t[(size_t)Dd * DFF];
__device__ __align__(128) float g_W2t[(size_t)DFF * Dd];

// ---------------------------------------------------------------------------
// PTX helpers
// ---------------------------------------------------------------------------
__device__ __forceinline__ void cp_async16(void* smem_dst, const void* gmem_src) {
    uint32_t dst = (uint32_t)__cvta_generic_to_shared(smem_dst);
    asm volatile("cp.async.cg.shared.global [%0], [%1], 16;\n" :: "r"(dst), "l"(gmem_src));
}
__device__ __forceinline__ void cp_commit() {
    asm volatile("cp.async.commit_group;\n");
}
template<int N>
__device__ __forceinline__ void cp_wait() {
    asm volatile("cp.async.wait_group %0;\n" :: "n"(N));
}
__device__ __forceinline__ float roundtf(float f) {
    uint32_t r;
    asm("cvt.rna.tf32.f32 %0, %1;" : "=r"(r) : "f"(f));
    return __uint_as_float(r);
}
__device__ __forceinline__ void mma_tf32(float* c, const uint32_t* a, const uint32_t* b) {
    asm volatile(
        "mma.sync.aligned.m16n8k8.row.col.f32.tf32.tf32.f32 "
        "{%0,%1,%2,%3}, {%4,%5,%6,%7}, {%8,%9}, {%0,%1,%2,%3};"
        : "+f"(c[0]), "+f"(c[1]), "+f"(c[2]), "+f"(c[3])
        : "r"(a[0]), "r"(a[1]), "r"(a[2]), "r"(a[3]), "r"(b[0]), "r"(b[1]));
}

// ---------------------------------------------------------------------------
// Round-to-tf32 copy (for raw weight matrices)
// ---------------------------------------------------------------------------
__global__ void round_copy_kernel(const float4* __restrict__ in,
                                  float4* __restrict__ out, int n4) {
    int i = blockIdx.x * 256 + threadIdx.x;
    if (i >= n4) return;
    float4 v = in[i];
    v.x = roundtf(v.x); v.y = roundtf(v.y);
    v.z = roundtf(v.z); v.w = roundtf(v.w);
    out[i] = v;
}

// ---------------------------------------------------------------------------
// Repack Wq/Wk/Wv [H,D,HD] into one row-major [D, 3*D] matrix (tf32-rounded)
// ---------------------------------------------------------------------------
__global__ void repack_qkv_kernel(const float* __restrict__ Wq,
                                  const float* __restrict__ Wk,
                                  const float* __restrict__ Wv,
                                  float* __restrict__ out) {
    int idx = blockIdx.x * 256 + threadIdx.x;
    int k = idx / NQKV;
    int n = idx - k * NQKV;
    int sel = n >> 11;
    int nn  = n & 2047;
    int h   = nn >> 9;
    int c   = nn & 511;
    const float* W = (sel == 0) ? Wq : (sel == 1) ? Wk : Wv;
    out[idx] = roundtf(W[((size_t)h * Dd + k) * HDd + c]);
}

// ---------------------------------------------------------------------------
// LayerNorm: one block per row (D=2048), 256 threads. Output tf32-rounded
// (it is consumed only as a GEMM A operand).
// ---------------------------------------------------------------------------
__global__ void ln_kernel(const float* __restrict__ x,
                          const float* __restrict__ g,
                          const float* __restrict__ b,
                          float* __restrict__ out) {
    int row = blockIdx.x;
    int t   = threadIdx.x;
    const float4* xr = (const float4*)(x + (size_t)row * Dd);
    float4 v0 = xr[t];
    float4 v1 = xr[t + 256];
    float s  = v0.x + v0.y + v0.z + v0.w + v1.x + v1.y + v1.z + v1.w;
    float sq = v0.x*v0.x + v0.y*v0.y + v0.z*v0.z + v0.w*v0.w
             + v1.x*v1.x + v1.y*v1.y + v1.z*v1.z + v1.w*v1.w;
    #pragma unroll
    for (int o = 16; o; o >>= 1) {
        s  += __shfl_xor_sync(0xffffffffu, s,  o);
        sq += __shfl_xor_sync(0xffffffffu, sq, o);
    }
    __shared__ float ss[8], ssq[8];
    int w = t >> 5;
    if ((t & 31) == 0) { ss[w] = s; ssq[w] = sq; }
    __syncthreads();
    float S = 0.f, SQ = 0.f;
    #pragma unroll
    for (int i = 0; i < 8; i++) { S += ss[i]; SQ += ssq[i]; }
    float mean = S * (1.f / Dd);
    float var  = SQ * (1.f / Dd) - mean * mean;
    float rstd = rsqrtf(var + LNEPS);

    const float4* gr = (const float4*)g;
    const float4* br = (const float4*)b;
    float4* o4 = (float4*)(out + (size_t)row * Dd);
    float4 gv = gr[t], bv = br[t], r;
    r.x = roundtf((v0.x - mean) * rstd * gv.x + bv.x);
    r.y = roundtf((v0.y - mean) * rstd * gv.y + bv.y);
    r.z = roundtf((v0.z - mean) * rstd * gv.z + bv.z);
    r.w = roundtf((v0.w - mean) * rstd * gv.w + bv.w);
    o4[t] = r;
    gv = gr[t + 256]; bv = br[t + 256];
    r.x = roundtf((v1.x - mean) * rstd * gv.x + bv.x);
    r.y = roundtf((v1.y - mean) * rstd * gv.y + bv.y);
    r.z = roundtf((v1.z - mean) * rstd * gv.z + bv.z);
    r.w = roundtf((v1.w - mean) * rstd * gv.w + bv.w);
    o4[t + 256] = r;
}

// ---------------------------------------------------------------------------
// tf32 tensor-core NN GEMM: C = A@B (+bias)(+resid)(relu)(round_out)
// 128x128x16 block tile, 256 threads = 8 warps (2x4), warp tile 64x32.
// Inputs MUST already be tf32-rounded fp32 — no cvt in the hot loop.
// 3-stage cp.async pipeline, one __syncthreads per k-tile.
// Batched over blockIdx.z with offsets sX1*(z/4) + sX2*(z%4).
// ---------------------------------------------------------------------------
#define APAD 20    // As row stride in floats
#define BPAD 136   // Bs row stride in floats
#define STAGES 3

__global__ void __launch_bounds__(256, 2)
tgemm_nn(const float* __restrict__ A, int lda, long long sA1, long long sA2,
         const float* __restrict__ B, int ldb, long long sB1, long long sB2,
         float* __restrict__ C, int ldc, long long sC1, long long sC2,
         int K,
         const float* __restrict__ bias,
         const float* __restrict__ resid, int ldr,
         int relu, int round_out) {
    int z  = blockIdx.z;
    int zb = z >> 2, zh = z & 3;
    A += sA1 * zb + sA2 * zh;
    B += sB1 * zb + sB2 * zh;
    C += sC1 * zb + sC2 * zh;

    const int m0 = blockIdx.y * 128;
    const int n0 = blockIdx.x * 128;
    const int tid  = threadIdx.x;
    const int lane = tid & 31;
    const int wid  = tid >> 5;
    const int g  = lane >> 2;        // groupID
    const int t4 = lane & 3;         // threadID in group
    const int mw = (wid >> 2) * 64;  // warp m offset
    const int nw = (wid & 3) * 32;   // warp n offset

    __shared__ __align__(16) float As[STAGES][128 * APAD];
    __shared__ __align__(16) float Bs[STAGES][16 * BPAD];

    const int a_row0 = tid >> 2;
    const int a_ch0  = (tid & 3) * 4;
    const int a_row1 = a_row0 + 64;
    const int b_row0 = tid >> 5;
    const int b_ch0  = (tid & 31) * 4;
    const int b_row1 = b_row0 + 8;

    auto issue = [&](int kt, int buf) {
        cp_async16(&As[buf][a_row0 * APAD + a_ch0],
                   A + (size_t)(m0 + a_row0) * lda + kt * 16 + a_ch0);
        cp_async16(&As[buf][a_row1 * APAD + a_ch0],
                   A + (size_t)(m0 + a_row1) * lda + kt * 16 + a_ch0);
        cp_async16(&Bs[buf][b_row0 * BPAD + b_ch0],
                   B + (size_t)(kt * 16 + b_row0) * ldb + n0 + b_ch0);
        cp_async16(&Bs[buf][b_row1 * BPAD + b_ch0],
                   B + (size_t)(kt * 16 + b_row1) * ldb + n0 + b_ch0);
        cp_commit();
    };

    float acc[4][4][4];
    #pragma unroll
    for (int mi = 0; mi < 4; mi++)
        #pragma unroll
        for (int ni = 0; ni < 4; ni++)
            #pragma unroll
            for (int q = 0; q < 4; q++) acc[mi][ni][q] = 0.f;

    const int nk = K >> 4;   // all call sites have nk >= 32
    issue(0, 0);
    issue(1, 1);

    for (int kt = 0; kt < nk; kt++) {
        const int cur = kt % STAGES;
        cp_wait<STAGES - 2>();     // tile kt resident (kt+1 may be in flight)
        __syncthreads();           // all warps done with buffer (kt-1)%3 == (kt+2)%3
        if (kt + 2 < nk) issue(kt + 2, (kt + 2) % STAGES);

        const float* __restrict__ Asc = As[cur];
        const float* __restrict__ Bsc = Bs[cur];
        #pragma unroll
        for (int ks = 0; ks < 2; ks++) {
            uint32_t af[4][4], bf[4][2];
            const int col = ks * 8 + t4;
            #pragma unroll
            for (int mi = 0; mi < 4; mi++) {
                const int r = mw + mi * 16 + g;
                af[mi][0] = __float_as_uint(Asc[r * APAD + col]);
                af[mi][1] = __float_as_uint(Asc[(r + 8) * APAD + col]);
                af[mi][2] = __float_as_uint(Asc[r * APAD + col + 4]);
                af[mi][3] = __float_as_uint(Asc[(r + 8) * APAD + col + 4]);
            }
            #pragma unroll
            for (int ni = 0; ni < 4; ni++) {
                const int cc = nw + ni * 8 + g;
                bf[ni][0] = __float_as_uint(Bsc[col * BPAD + cc]);
                bf[ni][1] = __float_as_uint(Bsc[(col + 4) * BPAD + cc]);
            }
            #pragma unroll
            for (int mi = 0; mi < 4; mi++)
                #pragma unroll
                for (int ni = 0; ni < 4; ni++)
                    mma_tf32(acc[mi][ni], af[mi], bf[ni]);
        }
    }

    // Epilogue
    #pragma unroll
    for (int mi = 0; mi < 4; mi++) {
        const int r0 = m0 + mw + mi * 16 + g;
        #pragma unroll
        for (int ni = 0; ni < 4; ni++) {
            const int c0 = n0 + nw + ni * 8 + t4 * 2;
            float bb0 = 0.f, bb1 = 0.f;
            if (bias) { bb0 = bias[c0]; bb1 = bias[c0 + 1]; }
            float v0 = acc[mi][ni][0] + bb0;
            float v1 = acc[mi][ni][1] + bb1;
            float v2 = acc[mi][ni][2] + bb0;
            float v3 = acc[mi][ni][3] + bb1;
            if (resid) {
                const float* R0 = resid + (size_t)r0 * ldr + c0;
                const float* R1 = resid + (size_t)(r0 + 8) * ldr + c0;
                v0 += R0[0]; v1 += R0[1];
                v2 += R1[0]; v3 += R1[1];
            }
            if (relu) {
                v0 = fmaxf(v0, 0.f); v1 = fmaxf(v1, 0.f);
                v2 = fmaxf(v2, 0.f); v3 = fmaxf(v3, 0.f);
            }
            if (round_out) {
                v0 = roundtf(v0); v1 = roundtf(v1);
                v2 = roundtf(v2); v3 = roundtf(v3);
            }
            *(float2*)&C[(size_t)r0 * ldc + c0]       = make_float2(v0, v1);
            *(float2*)&C[(size_t)(r0 + 8) * ldc + c0] = make_float2(v2, v3);
        }
    }
}

// ---------------------------------------------------------------------------
// Scores (fp32): S = scale * q k^T, causal mask. 64x64 tiles, NT.
// ---------------------------------------------------------------------------
__global__ void __launch_bounds__(256)
scores_nt_kernel(const float* __restrict__ QKV, float* __restrict__ S) {
    int z = blockIdx.z;
    int bb = z >> 2, hh = z & 3;
    const float* Aq = QKV + (size_t)bb * Tt * NQKV + hh * HDd;
    const float* Ak = Aq + Dd;
    float* Cs = S + (size_t)z * Tt * Tt;

    const int m0 = blockIdx.y * 64;
    const int n0 = blockIdx.x * 64;
    const int tid = threadIdx.x;
    const int ty = tid >> 4, tx = tid & 15;

    if (n0 > m0) {
        #pragma unroll
        for (int i = 0; i < 4; i++) {
            int gi = m0 + ty * 4 + i;
            float4 mm; mm.x = mm.y = mm.z = mm.w = -1e30f;
            *(float4*)&Cs[(size_t)gi * Tt + n0 + tx * 4] = mm;
        }
        return;
    }

    __shared__ __align__(16) float As[2][16][64];
    __shared__ __align__(16) float Bs[2][16][64];

    const int lrow = tid >> 2;
    const int lcol = (tid & 3) * 4;

    float4 ra, rb;
    auto loadT = [&](int kt) {
        ra = *(const float4*)(Aq + (size_t)(m0 + lrow) * NQKV + kt * 16 + lcol);
        rb = *(const float4*)(Ak + (size_t)(n0 + lrow) * NQKV + kt * 16 + lcol);
    };
    auto storeT = [&](int buf) {
        As[buf][lcol + 0][lrow] = ra.x; As[buf][lcol + 1][lrow] = ra.y;
        As[buf][lcol + 2][lrow] = ra.z; As[buf][lcol + 3][lrow] = ra.w;
        Bs[buf][lcol + 0][lrow] = rb.x; Bs[buf][lcol + 1][lrow] = rb.y;
        Bs[buf][lcol + 2][lrow] = rb.z; Bs[buf][lcol + 3][lrow] = rb.w;
    };

    float acc[4][4];
    #pragma unroll
    for (int i = 0; i < 4; i++)
        #pragma unroll
        for (int j = 0; j < 4; j++) acc[i][j] = 0.f;

    loadT(0); storeT(0);
    __syncthreads();

    const int nk = HDd / 16;
    for (int kt = 0; kt < nk; kt++) {
        int cur = kt & 1;
        if (kt + 1 < nk) loadT(kt + 1);
        #pragma unroll
        for (int kk = 0; kk < 16; kk++) {
            float a[4], bvv[4];
            *(float4*)a   = *(const float4*)&As[cur][kk][ty * 4];
            *(float4*)bvv = *(const float4*)&Bs[cur][kk][tx * 4];
            #pragma unroll
            for (int i = 0; i < 4; i++)
                #pragma unroll
                for (int j = 0; j < 4; j++)
                    acc[i][j] += a[i] * bvv[j];
        }
        if (kt + 1 < nk) {
            storeT(cur ^ 1);
            __syncthreads();
        }
    }

    const float scale = 0.044194173824159216f;
    #pragma unroll
    for (int i = 0; i < 4; i++) {
        int gi = m0 + ty * 4 + i;
        float v[4];
        #pragma unroll
        for (int j = 0; j < 4; j++) {
            int gj = n0 + tx * 4 + j;
            v[j] = (gj > gi) ? -1e30f : acc[i][j] * scale;
        }
        float4 o; o.x = v[0]; o.y = v[1]; o.z = v[2]; o.w = v[3];
        *(float4*)&Cs[(size_t)gi * Tt + n0 + tx * 4] = o;
    }
}

// ---------------------------------------------------------------------------
// Row softmax over T=512 entries. Output tf32-rounded (GEMM A operand).
// ---------------------------------------------------------------------------
__global__ void softmax_kernel(float* __restrict__ S) {
    int row = blockIdx.x;
    int t = threadIdx.x;
    float4* p = (float4*)(S + (size_t)row * Tt);
    float4 v = p[t];
    float m = fmaxf(fmaxf(v.x, v.y), fmaxf(v.z, v.w));
    #pragma unroll
    for (int o = 16; o; o >>= 1) m = fmaxf(m, __shfl_xor_sync(0xffffffffu, m, o));
    __shared__ float sm[4], ssum[4];
    int w = t >> 5;
    if ((t & 31) == 0) sm[w] = m;
    __syncthreads();
    m = fmaxf(fmaxf(sm[0], sm[1]), fmaxf(sm[2], sm[3]));
    v.x = expf(v.x - m); v.y = expf(v.y - m);
    v.z = expf(v.z - m); v.w = expf(v.w - m);
    float s = v.x + v.y + v.z + v.w;
    #pragma unroll
    for (int o = 16; o; o >>= 1) s += __shfl_xor_sync(0xffffffffu, s, o);
    if ((t & 31) == 0) ssum[w] = s;
    __syncthreads();
    s = ssum[0] + ssum[1] + ssum[2] + ssum[3];
    float inv = 1.f / s;
    v.x = roundtf(v.x * inv); v.y = roundtf(v.y * inv);
    v.z = roundtf(v.z * inv); v.w = roundtf(v.w * inv);
    p[t] = v;
}

// ---------------------------------------------------------------------------
// Host launcher
// ---------------------------------------------------------------------------
extern "C" void kernel_launch(void* const* d_in, const int* in_sizes, int n_in,
                              void* d_out, int out_size) {
    const float* x   = (const float*)d_in[0];
    const float* Wq  = (const float*)d_in[1];
    const float* Wk  = (const float*)d_in[2];
    const float* Wv  = (const float*)d_in[3];
    const float* Wo  = (const float*)d_in[4];
    const float* bo  = (const float*)d_in[5];
    const float* W1  = (const float*)d_in[6];
    const float* b1  = (const float*)d_in[7];
    const float* W2  = (const float*)d_in[8];
    const float* b2  = (const float*)d_in[9];
    const float* g1  = (const float*)d_in[10];
    const float* be1 = (const float*)d_in[11];
    const float* g2  = (const float*)d_in[12];
    const float* be2 = (const float*)d_in[13];
    float* out = (float*)d_out;

    float *p_wqkv, *p_ln, *p_qkv, *p_sc, *p_ctx, *p_ffn, *p_wot, *p_w1t, *p_w2t;
    cudaGetSymbolAddress((void**)&p_wqkv, g_Wqkv);
    cudaGetSymbolAddress((void**)&p_ln,   g_ln);
    cudaGetSymbolAddress((void**)&p_qkv,  g_qkv);
    cudaGetSymbolAddress((void**)&p_sc,   g_scores);
    cudaGetSymbolAddress((void**)&p_ctx,  g_ctx);
    cudaGetSymbolAddress((void**)&p_ffn,  g_ffn);
    cudaGetSymbolAddress((void**)&p_wot,  g_Wot);
    cudaGetSymbolAddress((void**)&p_w1t,  g_W1t);
    cudaGetSymbolAddress((void**)&p_w2t,  g_W2t);

    // 0) tf32-round weight copies
    round_copy_kernel<<<(Dd * Dd / 4 + 255) / 256, 256>>>(
        (const float4*)Wo, (float4*)p_wot, Dd * Dd / 4);
    round_copy_kernel<<<(Dd * DFF / 4 + 255) / 256, 256>>>(
        (const float4*)W1, (float4*)p_w1t, Dd * DFF / 4);
    round_copy_kernel<<<(DFF * Dd / 4 + 255) / 256, 256>>>(
        (const float4*)W2, (float4*)p_w2t, DFF * Dd / 4);

    // 1) repack QKV weights -> [D, 3D] (tf32-rounded)
    repack_qkv_kernel<<<(Dd * NQKV) / 256, 256>>>(Wq, Wk, Wv, p_wqkv);

    // 2) h = LN(x) (tf32-rounded)
    ln_kernel<<<BT, 256>>>(x, g1, be1, p_ln);

    // 3) QKV = h @ Wqkv (round_out: q,k,v all feed tf32 consumers)
    tgemm_nn<<<dim3(NQKV / 128, BT / 128, 1), 256>>>(
        p_ln, Dd, 0, 0,
        p_wqkv, NQKV, 0, 0,
        p_qkv, NQKV, 0, 0,
        Dd, nullptr, nullptr, 0, 0, 1);

    // 4) scores = scale * q k^T with causal mask (fp32)
    scores_nt_kernel<<<dim3(Tt / 64, Tt / 64, Bb * Hh), 256>>>(p_qkv, p_sc);

    // 5) softmax rows (tf32-rounded probs)
    softmax_kernel<<<Bb * Hh * Tt, 128>>>(p_sc);

    // 6) ctx_cat = attn @ v (round_out: feeds Wo GEMM)
    tgemm_nn<<<dim3(HDd / 128, Tt / 128, Bb * Hh), 256>>>(
        p_sc, Tt, (long long)Hh * Tt * Tt, (long long)Tt * Tt,
        p_qkv + 2 * Dd, NQKV, (long long)Tt * NQKV, HDd,
        p_ctx, Dd, (long long)Tt * Dd, HDd,
        HDd, nullptr, nullptr, 0, 0, 1);

    // 7) x2 = x + ctx_cat @ Wo + bo -> d_out (full fp32 output)
    tgemm_nn<<<dim3(Dd / 128, BT / 128, 1), 256>>>(
        p_ctx, Dd, 0, 0,
        p_wot, Dd, 0, 0,
        out, Dd, 0, 0,
        Dd, bo, x, Dd, 0, 0);

    // 8) h2 = LN(x2) (tf32-rounded)
    ln_kernel<<<BT, 256>>>(out, g2, be2, p_ln);

    // 9) u = relu(h2 @ W1 + b1) (round_out: feeds W2 GEMM)
    tgemm_nn<<<dim3(DFF / 128, BT / 128, 1), 256>>>(
        p_ln, Dd, 0, 0,
        p_w1t, DFF, 0, 0,
        p_ffn, DFF, 0, 0,
        Dd, b1, nullptr, 0, 1, 1);

    // 10) out = x2 + u @ W2 + b2 (resid = d_out in place, fp32 output)
    tgemm_nn<<<dim3(Dd / 128, BT / 128, 1), 256>>>(
        p_ffn, DFF, 0, 0,
        p_w2t, Dd, 0, 0,
        out, Dd, 0, 0,
        DFF, b2, out, Dd, 0, 0);
}

// round 7
// speedup vs baseline: 1.0112x; 1.0112x over previous
#include <cuda_runtime.h>
#include <math.h>
#include <stdint.h>

// Problem constants
#define Bb   16
#define Tt   512
#define Dd   2048
#define Hh   4
#define HDd  512
#define BT   8192          // B*T rows
#define NQKV 6144          // 3*D
#define DFF  8192          // 4*D
#define LNEPS 1e-5f

// ---------------------------------------------------------------------------
// Scratch (static __device__ arrays; no allocation allowed)
// ---------------------------------------------------------------------------
__device__ __align__(128) float g_Wqkv[(size_t)Dd * NQKV];
__device__ __align__(128) float g_ln[(size_t)BT * Dd];
__device__ __align__(128) float g_qkv[(size_t)BT * NQKV];
__device__ __align__(128) float g_scores[(size_t)Bb * Hh * Tt * Tt];
__device__ __align__(128) float g_ctx[(size_t)BT * Dd];
__device__ __align__(128) float g_ffn[(size_t)BT * DFF];
__device__ __align__(128) float g_Wot[(size_t)Dd * Dd];
__device__ __align__(128) float g_W1t[(size_t)Dd * DFF];
__device__ __align__(128) float g_W2t[(size_t)DFF * Dd];

// ---------------------------------------------------------------------------
// PTX helpers
// ---------------------------------------------------------------------------
__device__ __forceinline__ void cp_async16(void* smem_dst, const void* gmem_src) {
    uint32_t dst = (uint32_t)__cvta_generic_to_shared(smem_dst);
    asm volatile("cp.async.cg.shared.global [%0], [%1], 16;\n" :: "r"(dst), "l"(gmem_src));
}
__device__ __forceinline__ void cp_commit() {
    asm volatile("cp.async.commit_group;\n");
}
template<int N>
__device__ __forceinline__ void cp_wait() {
    asm volatile("cp.async.wait_group %0;\n" :: "n"(N));
}
__device__ __forceinline__ float roundtf(float f) {
    uint32_t r;
    asm("cvt.rna.tf32.f32 %0, %1;" : "=r"(r) : "f"(f));
    return __uint_as_float(r);
}
__device__ __forceinline__ void mma_tf32(float* c, const uint32_t* a, const uint32_t* b) {
    asm volatile(
        "mma.sync.aligned.m16n8k8.row.col.f32.tf32.tf32.f32 "
        "{%0,%1,%2,%3}, {%4,%5,%6,%7}, {%8,%9}, {%0,%1,%2,%3};"
        : "+f"(c[0]), "+f"(c[1]), "+f"(c[2]), "+f"(c[3])
        : "r"(a[0]), "r"(a[1]), "r"(a[2]), "r"(a[3]), "r"(b[0]), "r"(b[1]));
}

// ---------------------------------------------------------------------------
// Round-to-tf32 copy (for raw weight matrices)
// ---------------------------------------------------------------------------
__global__ void round_copy_kernel(const float4* __restrict__ in,
                                  float4* __restrict__ out, int n4) {
    int i = blockIdx.x * 256 + threadIdx.x;
    if (i >= n4) return;
    float4 v = in[i];
    v.x = roundtf(v.x); v.y = roundtf(v.y);
    v.z = roundtf(v.z); v.w = roundtf(v.w);
    out[i] = v;
}

// ---------------------------------------------------------------------------
// Repack Wq/Wk/Wv [H,D,HD] into one row-major [D, 3*D] matrix (tf32-rounded)
// ---------------------------------------------------------------------------
__global__ void repack_qkv_kernel(const float* __restrict__ Wq,
                                  const float* __restrict__ Wk,
                                  const float* __restrict__ Wv,
                                  float* __restrict__ out) {
    int idx = blockIdx.x * 256 + threadIdx.x;
    int k = idx / NQKV;
    int n = idx - k * NQKV;
    int sel = n >> 11;
    int nn  = n & 2047;
    int h   = nn >> 9;
    int c   = nn & 511;
    const float* W = (sel == 0) ? Wq : (sel == 1) ? Wk : Wv;
    out[idx] = roundtf(W[((size_t)h * Dd + k) * HDd + c]);
}

// ---------------------------------------------------------------------------
// LayerNorm: one block per row (D=2048), 256 threads. Output tf32-rounded
// (it is consumed only as a GEMM A operand, so this is identical to
// rounding at fragment-load time).
// ---------------------------------------------------------------------------
__global__ void ln_kernel(const float* __restrict__ x,
                          const float* __restrict__ g,
                          const float* __restrict__ b,
                          float* __restrict__ out) {
    int row = blockIdx.x;
    int t   = threadIdx.x;
    const float4* xr = (const float4*)(x + (size_t)row * Dd);
    float4 v0 = xr[t];
    float4 v1 = xr[t + 256];
    float s  = v0.x + v0.y + v0.z + v0.w + v1.x + v1.y + v1.z + v1.w;
    float sq = v0.x*v0.x + v0.y*v0.y + v0.z*v0.z + v0.w*v0.w
             + v1.x*v1.x + v1.y*v1.y + v1.z*v1.z + v1.w*v1.w;
    #pragma unroll
    for (int o = 16; o; o >>= 1) {
        s  += __shfl_xor_sync(0xffffffffu, s,  o);
        sq += __shfl_xor_sync(0xffffffffu, sq, o);
    }
    __shared__ float ss[8], ssq[8];
    int w = t >> 5;
    if ((t & 31) == 0) { ss[w] = s; ssq[w] = sq; }
    __syncthreads();
    float S = 0.f, SQ = 0.f;
    #pragma unroll
    for (int i = 0; i < 8; i++) { S += ss[i]; SQ += ssq[i]; }
    float mean = S * (1.f / Dd);
    float var  = SQ * (1.f / Dd) - mean * mean;
    float rstd = rsqrtf(var + LNEPS);

    const float4* gr = (const float4*)g;
    const float4* br = (const float4*)b;
    float4* o4 = (float4*)(out + (size_t)row * Dd);
    float4 gv = gr[t], bv = br[t], r;
    r.x = roundtf((v0.x - mean) * rstd * gv.x + bv.x);
    r.y = roundtf((v0.y - mean) * rstd * gv.y + bv.y);
    r.z = roundtf((v0.z - mean) * rstd * gv.z + bv.z);
    r.w = roundtf((v0.w - mean) * rstd * gv.w + bv.w);
    o4[t] = r;
    gv = gr[t + 256]; bv = br[t + 256];
    r.x = roundtf((v1.x - mean) * rstd * gv.x + bv.x);
    r.y = roundtf((v1.y - mean) * rstd * gv.y + bv.y);
    r.z = roundtf((v1.z - mean) * rstd * gv.z + bv.z);
    r.w = roundtf((v1.w - mean) * rstd * gv.w + bv.w);
    o4[t + 256] = r;
}

// ---------------------------------------------------------------------------
// tf32 tensor-core NN GEMM: C = A@B (+bias)(+resid)(relu)(round_out)
// 128x128x16 block tile, 256 threads = 8 warps (2x4), warp tile 64x32.
// Inputs MUST already be tf32-rounded fp32 — no cvt in the hot loop.
// 3-stage cp.async pipeline, one __syncthreads per k-tile.
// round_out: 0 = fp32 out, 1 = tf32-round all, 2 = tf32-round cols >= 4096
// (the V block of the packed QKV output; q,k stay fp32 for the scores kernel).
// Batched over blockIdx.z with offsets sX1*(z/4) + sX2*(z%4).
// ---------------------------------------------------------------------------
#define APAD 20    // As row stride in floats
#define BPAD 136   // Bs row stride in floats
#define STAGES 3

__global__ void __launch_bounds__(256, 2)
tgemm_nn(const float* __restrict__ A, int lda, long long sA1, long long sA2,
         const float* __restrict__ B, int ldb, long long sB1, long long sB2,
         float* __restrict__ C, int ldc, long long sC1, long long sC2,
         int K,
         const float* __restrict__ bias,
         const float* __restrict__ resid, int ldr,
         int relu, int round_out) {
    int z  = blockIdx.z;
    int zb = z >> 2, zh = z & 3;
    A += sA1 * zb + sA2 * zh;
    B += sB1 * zb + sB2 * zh;
    C += sC1 * zb + sC2 * zh;

    const int m0 = blockIdx.y * 128;
    const int n0 = blockIdx.x * 128;
    const int tid  = threadIdx.x;
    const int lane = tid & 31;
    const int wid  = tid >> 5;
    const int g  = lane >> 2;        // groupID
    const int t4 = lane & 3;         // threadID in group
    const int mw = (wid >> 2) * 64;  // warp m offset
    const int nw = (wid & 3) * 32;   // warp n offset

    __shared__ __align__(16) float As[STAGES][128 * APAD];
    __shared__ __align__(16) float Bs[STAGES][16 * BPAD];

    const int a_row0 = tid >> 2;
    const int a_ch0  = (tid & 3) * 4;
    const int a_row1 = a_row0 + 64;
    const int b_row0 = tid >> 5;
    const int b_ch0  = (tid & 31) * 4;
    const int b_row1 = b_row0 + 8;

    auto issue = [&](int kt, int buf) {
        cp_async16(&As[buf][a_row0 * APAD + a_ch0],
                   A + (size_t)(m0 + a_row0) * lda + kt * 16 + a_ch0);
        cp_async16(&As[buf][a_row1 * APAD + a_ch0],
                   A + (size_t)(m0 + a_row1) * lda + kt * 16 + a_ch0);
        cp_async16(&Bs[buf][b_row0 * BPAD + b_ch0],
                   B + (size_t)(kt * 16 + b_row0) * ldb + n0 + b_ch0);
        cp_async16(&Bs[buf][b_row1 * BPAD + b_ch0],
                   B + (size_t)(kt * 16 + b_row1) * ldb + n0 + b_ch0);
        cp_commit();
    };

    float acc[4][4][4];
    #pragma unroll
    for (int mi = 0; mi < 4; mi++)
        #pragma unroll
        for (int ni = 0; ni < 4; ni++)
            #pragma unroll
            for (int q = 0; q < 4; q++) acc[mi][ni][q] = 0.f;

    const int nk = K >> 4;   // all call sites have nk >= 32
    issue(0, 0);
    issue(1, 1);

    for (int kt = 0; kt < nk; kt++) {
        const int cur = kt % STAGES;
        cp_wait<STAGES - 2>();     // tile kt resident (kt+1 may be in flight)
        __syncthreads();           // all warps done with buffer (kt+2)%3
        if (kt + 2 < nk) issue(kt + 2, (kt + 2) % STAGES);

        const float* __restrict__ Asc = As[cur];
        const float* __restrict__ Bsc = Bs[cur];
        #pragma unroll
        for (int ks = 0; ks < 2; ks++) {
            uint32_t af[4][4], bf[4][2];
            const int col = ks * 8 + t4;
            #pragma unroll
            for (int mi = 0; mi < 4; mi++) {
                const int r = mw + mi * 16 + g;
                af[mi][0] = __float_as_uint(Asc[r * APAD + col]);
                af[mi][1] = __float_as_uint(Asc[(r + 8) * APAD + col]);
                af[mi][2] = __float_as_uint(Asc[r * APAD + col + 4]);
                af[mi][3] = __float_as_uint(Asc[(r + 8) * APAD + col + 4]);
            }
            #pragma unroll
            for (int ni = 0; ni < 4; ni++) {
                const int cc = nw + ni * 8 + g;
                bf[ni][0] = __float_as_uint(Bsc[col * BPAD + cc]);
                bf[ni][1] = __float_as_uint(Bsc[(col + 4) * BPAD + cc]);
            }
            #pragma unroll
            for (int mi = 0; mi < 4; mi++)
                #pragma unroll
                for (int ni = 0; ni < 4; ni++)
                    mma_tf32(acc[mi][ni], af[mi], bf[ni]);
        }
    }

    // Epilogue
    #pragma unroll
    for (int mi = 0; mi < 4; mi++) {
        const int r0 = m0 + mw + mi * 16 + g;
        #pragma unroll
        for (int ni = 0; ni < 4; ni++) {
            const int c0 = n0 + nw + ni * 8 + t4 * 2;
            float bb0 = 0.f, bb1 = 0.f;
            if (bias) { bb0 = bias[c0]; bb1 = bias[c0 + 1]; }
            float v0 = acc[mi][ni][0] + bb0;
            float v1 = acc[mi][ni][1] + bb1;
            float v2 = acc[mi][ni][2] + bb0;
            float v3 = acc[mi][ni][3] + bb1;
            if (resid) {
                const float* R0 = resid + (size_t)r0 * ldr + c0;
                const float* R1 = resid + (size_t)(r0 + 8) * ldr + c0;
                v0 += R0[0]; v1 += R0[1];
                v2 += R1[0]; v3 += R1[1];
            }
            if (relu) {
                v0 = fmaxf(v0, 0.f); v1 = fmaxf(v1, 0.f);
                v2 = fmaxf(v2, 0.f); v3 = fmaxf(v3, 0.f);
            }
            if (round_out == 1 || (round_out == 2 && c0 >= 4096)) {
                v0 = roundtf(v0); v1 = roundtf(v1);
                v2 = roundtf(v2); v3 = roundtf(v3);
            }
            *(float2*)&C[(size_t)r0 * ldc + c0]       = make_float2(v0, v1);
            *(float2*)&C[(size_t)(r0 + 8) * ldc + c0] = make_float2(v2, v3);
        }
    }
}

// ---------------------------------------------------------------------------
// Scores (fp32): S = scale * q k^T, causal mask. 64x64 tiles, NT.
// q,k arrive in full fp32 precision (QKV GEMM does NOT round them).
// ---------------------------------------------------------------------------
__global__ void __launch_bounds__(256)
scores_nt_kernel(const float* __restrict__ QKV, float* __restrict__ S) {
    int z = blockIdx.z;
    int bb = z >> 2, hh = z & 3;
    const float* Aq = QKV + (size_t)bb * Tt * NQKV + hh * HDd;
    const float* Ak = Aq + Dd;
    float* Cs = S + (size_t)z * Tt * Tt;

    const int m0 = blockIdx.y * 64;
    const int n0 = blockIdx.x * 64;
    const int tid = threadIdx.x;
    const int ty = tid >> 4, tx = tid & 15;

    if (n0 > m0) {
        #pragma unroll
        for (int i = 0; i < 4; i++) {
            int gi = m0 + ty * 4 + i;
            float4 mm; mm.x = mm.y = mm.z = mm.w = -1e30f;
            *(float4*)&Cs[(size_t)gi * Tt + n0 + tx * 4] = mm;
        }
        return;
    }

    __shared__ __align__(16) float As[2][16][64];
    __shared__ __align__(16) float Bs[2][16][64];

    const int lrow = tid >> 2;
    const int lcol = (tid & 3) * 4;

    float4 ra, rb;
    auto loadT = [&](int kt) {
        ra = *(const float4*)(Aq + (size_t)(m0 + lrow) * NQKV + kt * 16 + lcol);
        rb = *(const float4*)(Ak + (size_t)(n0 + lrow) * NQKV + kt * 16 + lcol);
    };
    auto storeT = [&](int buf) {
        As[buf][lcol + 0][lrow] = ra.x; As[buf][lcol + 1][lrow] = ra.y;
        As[buf][lcol + 2][lrow] = ra.z; As[buf][lcol + 3][lrow] = ra.w;
        Bs[buf][lcol + 0][lrow] = rb.x; Bs[buf][lcol + 1][lrow] = rb.y;
        Bs[buf][lcol + 2][lrow] = rb.z; Bs[buf][lcol + 3][lrow] = rb.w;
    };

    float acc[4][4];
    #pragma unroll
    for (int i = 0; i < 4; i++)
        #pragma unroll
        for (int j = 0; j < 4; j++) acc[i][j] = 0.f;

    loadT(0); storeT(0);
    __syncthreads();

    const int nk = HDd / 16;
    for (int kt = 0; kt < nk; kt++) {
        int cur = kt & 1;
        if (kt + 1 < nk) loadT(kt + 1);
        #pragma unroll
        for (int kk = 0; kk < 16; kk++) {
            float a[4], bvv[4];
            *(float4*)a   = *(const float4*)&As[cur][kk][ty * 4];
            *(float4*)bvv = *(const float4*)&Bs[cur][kk][tx * 4];
            #pragma unroll
            for (int i = 0; i < 4; i++)
                #pragma unroll
                for (int j = 0; j < 4; j++)
                    acc[i][j] += a[i] * bvv[j];
        }
        if (kt + 1 < nk) {
            storeT(cur ^ 1);
            __syncthreads();
        }
    }

    const float scale = 0.044194173824159216f;
    #pragma unroll
    for (int i = 0; i < 4; i++) {
        int gi = m0 + ty * 4 + i;
        float v[4];
        #pragma unroll
        for (int j = 0; j < 4; j++) {
            int gj = n0 + tx * 4 + j;
            v[j] = (gj > gi) ? -1e30f : acc[i][j] * scale;
        }
        float4 o; o.x = v[0]; o.y = v[1]; o.z = v[2]; o.w = v[3];
        *(float4*)&Cs[(size_t)gi * Tt + n0 + tx * 4] = o;
    }
}

// ---------------------------------------------------------------------------
// Row softmax over T=512 entries. Output tf32-rounded (GEMM A operand only).
// ---------------------------------------------------------------------------
__global__ void softmax_kernel(float* __restrict__ S) {
    int row = blockIdx.x;
    int t = threadIdx.x;
    float4* p = (float4*)(S + (size_t)row * Tt);
    float4 v = p[t];
    float m = fmaxf(fmaxf(v.x, v.y), fmaxf(v.z, v.w));
    #pragma unroll
    for (int o = 16; o; o >>= 1) m = fmaxf(m, __shfl_xor_sync(0xffffffffu, m, o));
    __shared__ float sm[4], ssum[4];
    int w = t >> 5;
    if ((t & 31) == 0) sm[w] = m;
    __syncthreads();
    m = fmaxf(fmaxf(sm[0], sm[1]), fmaxf(sm[2], sm[3]));
    v.x = expf(v.x - m); v.y = expf(v.y - m);
    v.z = expf(v.z - m); v.w = expf(v.w - m);
    float s = v.x + v.y + v.z + v.w;
    #pragma unroll
    for (int o = 16; o; o >>= 1) s += __shfl_xor_sync(0xffffffffu, s, o);
    if ((t & 31) == 0) ssum[w] = s;
    __syncthreads();
    s = ssum[0] + ssum[1] + ssum[2] + ssum[3];
    float inv = 1.f / s;
    v.x = roundtf(v.x * inv); v.y = roundtf(v.y * inv);
    v.z = roundtf(v.z * inv); v.w = roundtf(v.w * inv);
    p[t] = v;
}

// ---------------------------------------------------------------------------
// Host launcher
// ---------------------------------------------------------------------------
extern "C" void kernel_launch(void* const* d_in, const int* in_sizes, int n_in,
                              void* d_out, int out_size) {
    const float* x   = (const float*)d_in[0];
    const float* Wq  = (const float*)d_in[1];
    const float* Wk  = (const float*)d_in[2];
    const float* Wv  = (const float*)d_in[3];
    const float* Wo  = (const float*)d_in[4];
    const float* bo  = (const float*)d_in[5];
    const float* W1  = (const float*)d_in[6];
    const float* b1  = (const float*)d_in[7];
    const float* W2  = (const float*)d_in[8];
    const float* b2  = (const float*)d_in[9];
    const float* g1  = (const float*)d_in[10];
    const float* be1 = (const float*)d_in[11];
    const float* g2  = (const float*)d_in[12];
    const float* be2 = (const float*)d_in[13];
    float* out = (float*)d_out;

    float *p_wqkv, *p_ln, *p_qkv, *p_sc, *p_ctx, *p_ffn, *p_wot, *p_w1t, *p_w2t;
    cudaGetSymbolAddress((void**)&p_wqkv, g_Wqkv);
    cudaGetSymbolAddress((void**)&p_ln,   g_ln);
    cudaGetSymbolAddress((void**)&p_qkv,  g_qkv);
    cudaGetSymbolAddress((void**)&p_sc,   g_scores);
    cudaGetSymbolAddress((void**)&p_ctx,  g_ctx);
    cudaGetSymbolAddress((void**)&p_ffn,  g_ffn);
    cudaGetSymbolAddress((void**)&p_wot,  g_Wot);
    cudaGetSymbolAddress((void**)&p_w1t,  g_W1t);
    cudaGetSymbolAddress((void**)&p_w2t,  g_W2t);

    // 0) tf32-round weight copies
    round_copy_kernel<<<(Dd * Dd / 4 + 255) / 256, 256>>>(
        (const float4*)Wo, (float4*)p_wot, Dd * Dd / 4);
    round_copy_kernel<<<(Dd * DFF / 4 + 255) / 256, 256>>>(
        (const float4*)W1, (float4*)p_w1t, Dd * DFF / 4);
    round_copy_kernel<<<(DFF * Dd / 4 + 255) / 256, 256>>>(
        (const float4*)W2, (float4*)p_w2t, DFF * Dd / 4);

    // 1) repack QKV weights -> [D, 3D] (tf32-rounded)
    repack_qkv_kernel<<<(Dd * NQKV) / 256, 256>>>(Wq, Wk, Wv, p_wqkv);

    // 2) h = LN(x) (tf32-rounded)
    ln_kernel<<<BT, 256>>>(x, g1, be1, p_ln);

    // 3) QKV = h @ Wqkv. round_out=2: round ONLY the v block (cols >= 4096,
    //    consumed as tf32 MMA operand); q,k stay fp32 for the scores kernel.
    tgemm_nn<<<dim3(NQKV / 128, BT / 128, 1), 256>>>(
        p_ln, Dd, 0, 0,
        p_wqkv, NQKV, 0, 0,
        p_qkv, NQKV, 0, 0,
        Dd, nullptr, nullptr, 0, 0, 2);

    // 4) scores = scale * q k^T with causal mask (full fp32)
    scores_nt_kernel<<<dim3(Tt / 64, Tt / 64, Bb * Hh), 256>>>(p_qkv, p_sc);

    // 5) softmax rows (tf32-rounded probs)
    softmax_kernel<<<Bb * Hh * Tt, 128>>>(p_sc);

    // 6) ctx_cat = attn @ v (round_out: feeds Wo GEMM)
    tgemm_nn<<<dim3(HDd / 128, Tt / 128, Bb * Hh), 256>>>(
        p_sc, Tt, (long long)Hh * Tt * Tt, (long long)Tt * Tt,
        p_qkv + 2 * Dd, NQKV, (long long)Tt * NQKV, HDd,
        p_ctx, Dd, (long long)Tt * Dd, HDd,
        HDd, nullptr, nullptr, 0, 0, 1);

    // 7) x2 = x + ctx_cat @ Wo + bo -> d_out (full fp32 output)
    tgemm_nn<<<dim3(Dd / 128, BT / 128, 1), 256>>>(
        p_ctx, Dd, 0, 0,
        p_wot, Dd, 0, 0,
        out, Dd, 0, 0,
        Dd, bo, x, Dd, 0, 0);

    // 8) h2 = LN(x2) (tf32-rounded)
    ln_kernel<<<BT, 256>>>(out, g2, be2, p_ln);

    // 9) u = relu(h2 @ W1 + b1) (round_out: feeds W2 GEMM)
    tgemm_nn<<<dim3(DFF / 128, BT / 128, 1), 256>>>(
        p_ln, Dd, 0, 0,
        p_w1t, DFF, 0, 0,
        p_ffn, DFF, 0, 0,
        Dd, b1, nullptr, 0, 1, 1);

    // 10) out = x2 + u @ W2 + b2 (resid = d_out in place, fp32 output)
    tgemm_nn<<<dim3(Dd / 128, BT / 128, 1), 256>>>(
        p_ffn, DFF, 0, 0,
        p_w2t, Dd, 0, 0,
        out, Dd, 0, 0,
        DFF, b2, out, Dd, 0, 0);
}